// round 7
// baseline (speedup 1.0000x reference)
#include <cuda_runtime.h>
#include <cstdint>

// out = relu( row_mask ? (features + residuals[0] + residuals[1]) : 0 )
// features:  (256, 128, 1024) f32
// residuals: (2, 256, 128, 1024) f32
// mol_slice: (256, 2) int64 OR int32 (runtime-detected)
//
// 8 consecutive rows per block (same batch: 8 | 128), 128 threads, one
// 8-float (256-bit) slot per thread. Up to 24 independent v8 LDGs per
// thread, register-budgeted via __launch_bounds__(128, 3) (~168 regs) so
// ptxas keeps a deep load pipeline without spilling. f+r0 folded early to
// recycle registers. Masked rows: zero store only, no loads.

#define BATCH 256
#define MAX_ATOM 128
#define N_FEAT 1024
#define THREADS 128        // N_FEAT / 8
#define ROWS_PER_BLK 8

struct f8 { float v[8]; };

__device__ __forceinline__ f8 ldnc8(const float* p) {
    f8 r;
    asm volatile("ld.global.nc.v8.f32 {%0,%1,%2,%3,%4,%5,%6,%7}, [%8];"
                 : "=f"(r.v[0]), "=f"(r.v[1]), "=f"(r.v[2]), "=f"(r.v[3]),
                   "=f"(r.v[4]), "=f"(r.v[5]), "=f"(r.v[6]), "=f"(r.v[7])
                 : "l"(p));
    return r;
}

__device__ __forceinline__ void stcs8(float* p, const f8& r) {
    asm volatile("st.global.cs.v8.f32 [%0], {%1,%2,%3,%4,%5,%6,%7,%8};"
                 :: "l"(p),
                    "f"(r.v[0]), "f"(r.v[1]), "f"(r.v[2]), "f"(r.v[3]),
                    "f"(r.v[4]), "f"(r.v[5]), "f"(r.v[6]), "f"(r.v[7])
                 : "memory");
}

__global__ __launch_bounds__(THREADS, 3)
void dense_block_end_kernel(const float* __restrict__ features,
                            const float* __restrict__ residuals,
                            const void*  __restrict__ mol_slice,
                            float* __restrict__ out)
{
    const int row0 = blockIdx.x * ROWS_PER_BLK;
    const int b    = row0 >> 7;                  // / MAX_ATOM (8 | 128)
    const int a0   = row0 & (MAX_ATOM - 1);

    // mol_slice dtype sniff:
    //   int32: [M0, 1024, M1, 1024, ...] -> word[1] == 1024
    //   int64: [M0, 0, 1024, 0, ...]     -> word[1] == 0 (hi word, M <= 128)
    const int* ms32 = (const int*)mol_slice;
    int n_atoms;
    if (ms32[1] == N_FEAT) {
        n_atoms = ms32[2 * b];
    } else {
        n_atoms = (int)((const long long*)mol_slice)[2 * b];
    }

    const size_t res_stride = (size_t)BATCH * MAX_ATOM * N_FEAT;
    const size_t base0 = (size_t)row0 * N_FEAT + threadIdx.x * 8;

    // Phase 1: front-batch f and r0 loads for all active rows, fold to p=f+r0
    // as results land (recycles f/r0 registers under the launch_bounds cap).
    f8 p[ROWS_PER_BLK], r1[ROWS_PER_BLK];
    bool act[ROWS_PER_BLK];

    {
        f8 f[ROWS_PER_BLK], r0[ROWS_PER_BLK];
        #pragma unroll
        for (int i = 0; i < ROWS_PER_BLK; i++) {
            act[i] = (a0 + i) < n_atoms;
            const size_t base = base0 + (size_t)i * N_FEAT;
            if (act[i]) {
                f[i]  = ldnc8(features + base);
                r0[i] = ldnc8(residuals + base);
            }
        }
        #pragma unroll
        for (int i = 0; i < ROWS_PER_BLK; i++) {
            if (act[i]) {
                #pragma unroll
                for (int j = 0; j < 8; j++) p[i].v[j] = f[i].v[j] + r0[i].v[j];
            }
        }
    }

    // Phase 2: r1 loads (another wave of independent v8 LDGs).
    #pragma unroll
    for (int i = 0; i < ROWS_PER_BLK; i++) {
        if (act[i]) {
            const size_t base = base0 + (size_t)i * N_FEAT;
            r1[i] = ldnc8(residuals + res_stride + base);
        }
    }

    // Phase 3: relu + streaming store (zeros for masked rows).
    #pragma unroll
    for (int i = 0; i < ROWS_PER_BLK; i++) {
        const size_t base = base0 + (size_t)i * N_FEAT;
        f8 v;
        #pragma unroll
        for (int j = 0; j < 8; j++) v.v[j] = 0.f;
        if (act[i]) {
            #pragma unroll
            for (int j = 0; j < 8; j++)
                v.v[j] = fmaxf(p[i].v[j] + r1[i].v[j], 0.f);
        }
        stcs8(out + base, v);
    }
}

extern "C" void kernel_launch(void* const* d_in, const int* in_sizes, int n_in,
                              void* d_out, int out_size)
{
    const float* features  = (const float*)d_in[0];
    const float* residuals = (const float*)d_in[1];
    const void*  mol_slice = d_in[2];
    float* out = (float*)d_out;

    dense_block_end_kernel<<<(BATCH * MAX_ATOM) / ROWS_PER_BLK, THREADS>>>(
        features, residuals, mol_slice, out);
}